// round 14
// baseline (speedup 1.0000x reference)
#include <cuda_runtime.h>
#include <cuda_fp16.h>
#include <cstdint>

#define BB 32
#define CC 128
#define TLEN 16000
#define NTO 126              // valid output columns per block (EVEN); f/g computes 128
#define NBLK 127             // ceil(16000/126)

// smem (u32 units): xt = x tile, t-major half2{cin,cin+1}, stride 68 (banks 4g+q bijective)
//                   ot = o tile, t-major half2{cout,cout+1}, stride 68, 129 rows (row 128 = pad)
#define XTS   68
#define XROWS 132            // j=0 <-> t = tbase-3 ; 64*132 = 8448 = 33*256
#define OT_U32_OFF (XROWS * XTS)                   // 8976
#define SMEMF ((XROWS * XTS + 129 * XTS) * 4)      // 70992 B

__device__ uint4 g_wtA[3 * 4096];            // fp16 fragment-packed weights

// ---------------- helpers ----------------
__device__ __forceinline__ uint32_t h2pack(float lo, float hi) {
    __half2 h = __floats2half2_rn(lo, hi);
    return *(uint32_t*)&h;
}

__device__ __forceinline__ void mma_f16(float* d, const uint32_t* a, const uint32_t* b) {
    asm volatile(
        "mma.sync.aligned.m16n8k16.row.col.f32.f16.f16.f32 "
        "{%0,%1,%2,%3}, {%4,%5,%6,%7}, {%8,%9}, {%0,%1,%2,%3};"
        : "+f"(d[0]), "+f"(d[1]), "+f"(d[2]), "+f"(d[3])
        : "r"(a[0]), "r"(a[1]), "r"(a[2]), "r"(a[3]), "r"(b[0]), "r"(b[1]));
}

// ---------------- weight fragment pre-pack (fp16) ----------------
// uint4 idx = conv*4096 + c*1024 + kf*256 + mi*128 + wm*32 + lane
// tap = kf>>1, cb = c*32 + (kf&1)*16 + qc*2, r0 = wm*32 + mi*16 + grp
__global__ void k_transpose(const float* __restrict__ wf,
                            const float* __restrict__ wg,
                            const float* __restrict__ ws) {
    int idx = blockIdx.x * 256 + threadIdx.x;
    if (idx >= 3 * 4096) return;
    int lane = idx & 31;
    int wm   = (idx >> 5) & 3;
    int mi   = (idx >> 7) & 1;
    int kf   = (idx >> 8) & 3;
    int c    = (idx >> 10) & 3;
    int conv = idx >> 12;
    int grp = lane >> 2, qc = lane & 3;
    int r0  = wm * 32 + mi * 16 + grp;
    int cb  = c * 32 + (kf & 1) * 16 + qc * 2;
    int tap = kf >> 1;
    const float* src = (conv == 0) ? wf : ((conv == 1) ? wg : ws);
#define WV(r, ci) src[((r) * CC + (ci)) * 2 + tap]
    uint4 v;
    v.x = h2pack(WV(r0, cb),     WV(r0, cb + 1));
    v.y = h2pack(WV(r0 + 8, cb), WV(r0 + 8, cb + 1));
    v.z = h2pack(WV(r0, cb + 8),     WV(r0, cb + 9));
    v.w = h2pack(WV(r0 + 8, cb + 8), WV(r0 + 8, cb + 9));
#undef WV
    g_wtA[idx] = v;
}

// ---------------- fused: f/g convs -> gated act (smem) -> skip conv -> residual ----
__global__ __launch_bounds__(256, 1) void k_fused(const float* __restrict__ x,
                                                  float* __restrict__ out,
                                                  float* __restrict__ skip) {
    extern __shared__ uint32_t smu[];
    uint32_t* xt = smu;                  // [132 j][68], j=0 <-> t = tbase-3
    uint32_t* ot = smu + OT_U32_OFF;     // [129 j][68], j   <-> t = tbase-1+j

    const int tid  = threadIdx.x;
    const int wid  = tid >> 5;
    const int lane = tid & 31;
    const int grp  = lane >> 2;
    const int qc   = lane & 3;
    const int wm   = wid & 3;            // phase A: M group (32 rows)
    const int wn   = wid >> 2;           // phase A: N group (64 cols)
    const int b     = blockIdx.y;
    const int tbase = blockIdx.x * NTO;  // EVEN
    const float* xb = x + (size_t)b * CC * TLEN;

    // ---- stage x tile once (132 rows x 64 cin-pairs = 8448 = 33*256) ----
#pragma unroll
    for (int it = 0; it < 33; it++) {
        int idx = it * 256 + tid;
        int cp = idx / XROWS;            // 0..63
        int j  = idx - cp * XROWS;       // 0..131 (lane-contiguous -> coalesced LDG)
        int t  = tbase - 3 + j;
        float lo = 0.f, hi = 0.f;
        if (t >= 0 && t < TLEN) {
            lo = xb[(size_t)(2 * cp) * TLEN + t];
            hi = xb[(size_t)(2 * cp + 1) * TLEN + t];
        }
        xt[j * XTS + cp] = h2pack(lo, hi);
    }
    __syncthreads();

    // ================= Phase A: f/g GEMMs, warp tile 32 x 64 ====
    float accf[2][8][4], accg[2][8][4];
#pragma unroll
    for (int mi = 0; mi < 2; mi++)
#pragma unroll
        for (int ni = 0; ni < 8; ni++)
#pragma unroll
            for (int i = 0; i < 4; i++) { accf[mi][ni][i] = 0.f; accg[mi][ni][i] = 0.f; }

    {
        const uint4* gwf = g_wtA + (wm * 32 + lane);
        const uint4* gwg = gwf + 4096;
        const uint32_t* xtw = xt + (wn * 64 + grp) * XTS + qc;
        for (int c = 0; c < 4; c++) {
#pragma unroll
            for (int kf = 0; kf < 4; kf++) {
                const int tap2 = (kf >> 1) * 2;
                const int cpb  = c * 16 + (kf & 1) * 8;
                uint32_t bfr[8][2];
#pragma unroll
                for (int ni = 0; ni < 8; ni++) {
                    const uint32_t* p = xtw + (ni * 8 + tap2) * XTS + cpb;
                    bfr[ni][0] = p[0];
                    bfr[ni][1] = p[4];
                }
#pragma unroll
                for (int mi = 0; mi < 2; mi++) {
                    uint4 af = gwf[c * 1024 + kf * 256 + mi * 128];
                    uint4 ag = gwg[c * 1024 + kf * 256 + mi * 128];
#pragma unroll
                    for (int ni = 0; ni < 8; ni++) {
                        mma_f16(accf[mi][ni], (const uint32_t*)&af, bfr[ni]);
                        mma_f16(accg[mi][ni], (const uint32_t*)&ag, bfr[ni]);
                    }
                }
            }
        }
    }

    // zero ot pad row 128 (feeds masked columns only; must be finite)
    if (tid < XTS) ot[128 * XTS + tid] = 0;

    // ---- Phase A epilogue: gated act -> ot via shfl pack ----
    {
#pragma unroll
        for (int mi = 0; mi < 2; mi++)
#pragma unroll
            for (int ni = 0; ni < 8; ni++) {
                float f0 = accf[mi][ni][0], f1 = accf[mi][ni][1];
                float f2 = accf[mi][ni][2], f3 = accf[mi][ni][3];
                float g0 = accg[mi][ni][0], g1 = accg[mi][ni][1];
                float g2 = accg[mi][ni][2], g3 = accg[mi][ni][3];
                float v0 = (1.f - __fdividef(2.f, 1.f + __expf(2.f * f0))) * __fdividef(1.f, 1.f + __expf(-g0));
                float v1 = (1.f - __fdividef(2.f, 1.f + __expf(2.f * f1))) * __fdividef(1.f, 1.f + __expf(-g1));
                float v2 = (1.f - __fdividef(2.f, 1.f + __expf(2.f * f2))) * __fdividef(1.f, 1.f + __expf(-g2));
                float v3 = (1.f - __fdividef(2.f, 1.f + __expf(2.f * f3))) * __fdividef(1.f, 1.f + __expf(-g3));
                float u0 = __shfl_xor_sync(0xFFFFFFFF, v0, 4);
                float u1 = __shfl_xor_sync(0xFFFFFFFF, v1, 4);
                float u2 = __shfl_xor_sync(0xFFFFFFFF, v2, 4);
                float u3 = __shfl_xor_sync(0xFFFFFFFF, v3, 4);
                int t0 = wn * 64 + ni * 8 + 2 * qc;
                int cp = wm * 16 + mi * 8 + (grp >> 1);
                if (!(grp & 1)) {          // even grp owns column t0
                    ot[t0 * XTS + cp]     = h2pack(v0, u0);   // rows r0, r0+1
                    ot[t0 * XTS + cp + 4] = h2pack(v2, u2);   // rows r0+8, r0+9
                } else {                   // odd grp owns column t0+1
                    ot[(t0 + 1) * XTS + cp]     = h2pack(u1, v1);
                    ot[(t0 + 1) * XTS + cp + 4] = h2pack(u3, v3);
                }
            }
    }
    __syncthreads();   // ot complete, cross-warp visible

    // ================= Phase B: skip GEMM, 4 warps x (32 rows x 128 cols) =================
    if (wid < 4) {
        float acc[2][16][4];
#pragma unroll
        for (int mi = 0; mi < 2; mi++)
#pragma unroll
            for (int ni = 0; ni < 16; ni++)
#pragma unroll
                for (int i = 0; i < 4; i++) acc[mi][ni][i] = 0.f;

        const uint4* gws = g_wtA + 2 * 4096 + (wid * 32 + lane);
        const uint32_t* otw = ot + grp * XTS + qc;
        for (int c = 0; c < 4; c++) {
#pragma unroll
            for (int kf = 0; kf < 4; kf++) {
                const int tap = kf >> 1;
                const int cpb = c * 16 + (kf & 1) * 8;
#pragma unroll
                for (int mi = 0; mi < 2; mi++) {
                    uint4 a4 = gws[c * 1024 + kf * 256 + mi * 128];
#pragma unroll
                    for (int ni = 0; ni < 16; ni++) {
                        uint32_t bfr[2];
                        const uint32_t* p = otw + (ni * 8 + tap) * XTS + cpb;
                        bfr[0] = p[0];
                        bfr[1] = p[4];
                        mma_f16(acc[mi][ni], (const uint32_t*)&a4, bfr);
                    }
                }
            }
        }

        // ---- Phase B epilogue: direct aligned STG.64 (skip = D, out = D + x) ----
        float* outb  = out  + (size_t)b * CC * TLEN;
        float* skipb = skip + (size_t)b * CC * TLEN;
#pragma unroll
        for (int mi = 0; mi < 2; mi++)
#pragma unroll
            for (int ni = 0; ni < 16; ni++) {
                int np0 = ni * 8 + 2 * qc;               // even, 0..126
                int t0  = tbase + np0;                   // even -> float2 aligned
                int r0  = wid * 32 + mi * 16 + grp;
                if (np0 < NTO && t0 + 1 < TLEN) {
#pragma unroll
                    for (int h = 0; h < 2; h++) {
                        size_t off = (size_t)(r0 + h * 8) * TLEN + t0;
                        float d0 = acc[mi][ni][h * 2], d1 = acc[mi][ni][h * 2 + 1];
                        float2 xr = *(const float2*)(xb + off);
                        *(float2*)(skipb + off) = make_float2(d0, d1);
                        *(float2*)(outb  + off) = make_float2(d0 + xr.x, d1 + xr.y);
                    }
                } else if (np0 < NTO && t0 < TLEN) {     // single trailing column
#pragma unroll
                    for (int h = 0; h < 2; h++) {
                        size_t off = (size_t)(r0 + h * 8) * TLEN + t0;
                        float d0 = acc[mi][ni][h * 2];
                        skipb[off] = d0;
                        outb[off]  = d0 + xb[off];
                    }
                }
            }
    }
}

extern "C" void kernel_launch(void* const* d_in, const int* in_sizes, int n_in,
                              void* d_out, int out_size) {
    const float* x  = (const float*)d_in[0];
    const float* wf = (const float*)d_in[1];
    const float* wg = (const float*)d_in[2];
    const float* ws = (const float*)d_in[3];

    float* out  = (float*)d_out;
    float* skip = out + (size_t)BB * CC * TLEN;

    cudaFuncSetAttribute(k_fused, cudaFuncAttributeMaxDynamicSharedMemorySize, SMEMF);

    k_transpose<<<(3 * 4096 + 255) / 256, 256>>>(wf, wg, ws);

    dim3 grid(NBLK, BB);
    k_fused<<<grid, 256, SMEMF>>>(x, out, skip);
}

// round 16
// speedup vs baseline: 1.3715x; 1.3715x over previous
#include <cuda_runtime.h>
#include <cuda_fp16.h>
#include <cstdint>

#define BB 32
#define CC 128
#define TLEN 16000
#define NTO 62               // valid output columns per block (EVEN -> aligned float2 stores)
#define NBLK 259             // ceil(16000/62)

// smem (u32 units): xt = x tile, t-major half2{cin,cin+1}, stride 68, XOR-swizzled low bits
//                   ot = o tile, t-major half2{cout,cout+1}, stride 68, 65 rows (row 64 = pad)
#define XTS   68
#define XROWS 68
#define OT_U32_OFF (XROWS * XTS)             // 4624
#define SMEMF ((XROWS * XTS + 65 * XTS) * 4) // 36176 B

__device__ uint4 g_wtA[3 * 4096];            // fp16 fragment-packed weights

// ---------------- helpers ----------------
__device__ __forceinline__ uint32_t h2pack(float lo, float hi) {
    __half2 h = __floats2half2_rn(lo, hi);
    return *(uint32_t*)&h;
}

__device__ __forceinline__ void mma_f16(float* d, const uint32_t* a, const uint32_t* b) {
    asm volatile(
        "mma.sync.aligned.m16n8k16.row.col.f32.f16.f16.f32 "
        "{%0,%1,%2,%3}, {%4,%5,%6,%7}, {%8,%9}, {%0,%1,%2,%3};"
        : "+f"(d[0]), "+f"(d[1]), "+f"(d[2]), "+f"(d[3])
        : "r"(a[0]), "r"(a[1]), "r"(a[2]), "r"(a[3]), "r"(b[0]), "r"(b[1]));
}

// ---------------- weight fragment pre-pack (fp16) ----------------
// uint4 idx = conv*4096 + c*1024 + kf*256 + mi*128 + wm*32 + lane
// tap = kf>>1, cb = c*32 + (kf&1)*16 + qc*2, r0 = wm*32 + mi*16 + grp
__global__ void k_transpose(const float* __restrict__ wf,
                            const float* __restrict__ wg,
                            const float* __restrict__ ws) {
    int idx = blockIdx.x * 256 + threadIdx.x;
    if (idx >= 3 * 4096) return;
    int lane = idx & 31;
    int wm   = (idx >> 5) & 3;
    int mi   = (idx >> 7) & 1;
    int kf   = (idx >> 8) & 3;
    int c    = (idx >> 10) & 3;
    int conv = idx >> 12;
    int grp = lane >> 2, qc = lane & 3;
    int r0  = wm * 32 + mi * 16 + grp;
    int cb  = c * 32 + (kf & 1) * 16 + qc * 2;
    int tap = kf >> 1;
    const float* src = (conv == 0) ? wf : ((conv == 1) ? wg : ws);
#define WV(r, ci) src[((r) * CC + (ci)) * 2 + tap]
    uint4 v;
    v.x = h2pack(WV(r0, cb),     WV(r0, cb + 1));
    v.y = h2pack(WV(r0 + 8, cb), WV(r0 + 8, cb + 1));
    v.z = h2pack(WV(r0, cb + 8),     WV(r0, cb + 9));
    v.w = h2pack(WV(r0 + 8, cb + 8), WV(r0 + 8, cb + 9));
#undef WV
    g_wtA[idx] = v;
}

// ---------------- fused: f/g convs -> gated act (smem) -> skip conv -> residual ----
__global__ __launch_bounds__(256, 2) void k_fused(const float* __restrict__ x,
                                                  float* __restrict__ out,
                                                  float* __restrict__ skip) {
    extern __shared__ uint32_t smu[];
    uint32_t* xt = smu;                  // [68 j][68], swizzled: addr = j*68 + (cp ^ ((j>>3)&3))
    uint32_t* ot = smu + OT_U32_OFF;     // [65 j][68], plain; j <-> t = tbase-1+j

    const int tid  = threadIdx.x;
    const int wid  = tid >> 5;
    const int lane = tid & 31;
    const int grp  = lane >> 2;
    const int qc   = lane & 3;
    const int wm   = wid & 3;
    const int wn   = wid >> 2;
    const int b     = blockIdx.y;
    const int tbase = blockIdx.x * NTO;  // EVEN
    const float* xb = x + (size_t)b * CC * TLEN;

    // ---- stage x tile once (68 rows x 64 cin-pairs = 4352 = 17*256), swizzled STS ----
#pragma unroll
    for (int it = 0; it < 17; it++) {
        int idx = it * 256 + tid;
        int cp = idx / XROWS;            // 0..63
        int j  = idx - cp * XROWS;       // 0..67 (lane-contiguous -> coalesced LDG)
        int t  = tbase - 3 + j;
        float lo = 0.f, hi = 0.f;
        if (t >= 0 && t < TLEN) {
            lo = xb[(size_t)(2 * cp) * TLEN + t];
            hi = xb[(size_t)(2 * cp + 1) * TLEN + t];
        }
        xt[j * XTS + (cp ^ ((j >> 3) & 3))] = h2pack(lo, hi);
    }
    __syncthreads();

    // ================= Phase A: f/g GEMMs (fragments direct from swizzled xt) ====
    float accf[2][4][4], accg[2][4][4];
#pragma unroll
    for (int mi = 0; mi < 2; mi++)
#pragma unroll
        for (int ni = 0; ni < 4; ni++)
#pragma unroll
            for (int i = 0; i < 4; i++) { accf[mi][ni][i] = 0.f; accg[mi][ni][i] = 0.f; }

    {
        const uint4* gwf = g_wtA + (wm * 32 + lane);
        const uint4* gwg = gwf + 4096;
        const int wnb = wn * 32 + grp;
        for (int c = 0; c < 4; c++) {
#pragma unroll
            for (int kf = 0; kf < 4; kf++) {
                const int tap2 = (kf >> 1) * 2;
                const int cpb  = c * 16 + (kf & 1) * 8;
                uint32_t bfr[4][2];
#pragma unroll
                for (int ni = 0; ni < 4; ni++) {
                    int j = wnb + ni * 8 + tap2;          // tap0: t-2, tap1: t
                    const uint32_t* row = xt + j * XTS + (cpb + (qc ^ ((j >> 3) & 3)));
                    bfr[ni][0] = row[0];
                    bfr[ni][1] = row[4];
                }
#pragma unroll
                for (int mi = 0; mi < 2; mi++) {
                    uint4 af = gwf[c * 1024 + kf * 256 + mi * 128];
                    uint4 ag = gwg[c * 1024 + kf * 256 + mi * 128];
#pragma unroll
                    for (int ni = 0; ni < 4; ni++) {
                        mma_f16(accf[mi][ni], (const uint32_t*)&af, bfr[ni]);
                        mma_f16(accg[mi][ni], (const uint32_t*)&ag, bfr[ni]);
                    }
                }
            }
        }
    }

    // zero ot pad row 64 (feeds masked columns only; must be finite)
    if (tid < XTS) ot[64 * XTS + tid] = 0;

    // ---- Phase A epilogue: gated act -> ot via shfl pack (ot unswizzled) ----
    {
#pragma unroll
        for (int mi = 0; mi < 2; mi++)
#pragma unroll
            for (int ni = 0; ni < 4; ni++) {
                float f0 = accf[mi][ni][0], f1 = accf[mi][ni][1];
                float f2 = accf[mi][ni][2], f3 = accf[mi][ni][3];
                float g0 = accg[mi][ni][0], g1 = accg[mi][ni][1];
                float g2 = accg[mi][ni][2], g3 = accg[mi][ni][3];
                float v0 = (1.f - __fdividef(2.f, 1.f + __expf(2.f * f0))) * __fdividef(1.f, 1.f + __expf(-g0));
                float v1 = (1.f - __fdividef(2.f, 1.f + __expf(2.f * f1))) * __fdividef(1.f, 1.f + __expf(-g1));
                float v2 = (1.f - __fdividef(2.f, 1.f + __expf(2.f * f2))) * __fdividef(1.f, 1.f + __expf(-g2));
                float v3 = (1.f - __fdividef(2.f, 1.f + __expf(2.f * f3))) * __fdividef(1.f, 1.f + __expf(-g3));
                float u0 = __shfl_xor_sync(0xFFFFFFFF, v0, 4);
                float u1 = __shfl_xor_sync(0xFFFFFFFF, v1, 4);
                float u2 = __shfl_xor_sync(0xFFFFFFFF, v2, 4);
                float u3 = __shfl_xor_sync(0xFFFFFFFF, v3, 4);
                int t0 = wn * 32 + ni * 8 + 2 * qc;
                int cp = wm * 16 + mi * 8 + (grp >> 1);
                if (!(grp & 1)) {          // even grp owns column t0
                    ot[t0 * XTS + cp]     = h2pack(v0, u0);   // rows r0, r0+1
                    ot[t0 * XTS + cp + 4] = h2pack(v2, u2);   // rows r0+8, r0+9
                } else {                   // odd grp owns column t0+1
                    ot[(t0 + 1) * XTS + cp]     = h2pack(u1, v1);
                    ot[(t0 + 1) * XTS + cp + 4] = h2pack(u3, v3);
                }
            }
    }
    __syncthreads();   // ot complete, cross-warp visible

    // ================= Phase B: skip GEMM, 4 warps x (32 rows x 64 cols) =================
    if (wid < 4) {
        float acc[2][8][4];
#pragma unroll
        for (int mi = 0; mi < 2; mi++)
#pragma unroll
            for (int ni = 0; ni < 8; ni++)
#pragma unroll
                for (int i = 0; i < 4; i++) acc[mi][ni][i] = 0.f;

        const uint4* gws = g_wtA + 2 * 4096 + (wid * 32 + lane);
        const uint32_t* otw = ot + grp * XTS + qc;
        for (int c = 0; c < 4; c++) {
#pragma unroll
            for (int kf = 0; kf < 4; kf++) {
                const int tap = kf >> 1;
                const int cpb = c * 16 + (kf & 1) * 8;
                uint32_t bfr[8][2];
#pragma unroll
                for (int ni = 0; ni < 8; ni++) {
                    const uint32_t* p = otw + (ni * 8 + tap) * XTS + cpb;
                    bfr[ni][0] = p[0];
                    bfr[ni][1] = p[4];
                }
#pragma unroll
                for (int mi = 0; mi < 2; mi++) {
                    uint4 a4 = gws[c * 1024 + kf * 256 + mi * 128];
#pragma unroll
                    for (int ni = 0; ni < 8; ni++)
                        mma_f16(acc[mi][ni], (const uint32_t*)&a4, bfr[ni]);
                }
            }
        }

        // ---- Phase B epilogue: streaming stores (skip = D, out = D + x) ----
        float* outb  = out  + (size_t)b * CC * TLEN;
        float* skipb = skip + (size_t)b * CC * TLEN;
#pragma unroll
        for (int mi = 0; mi < 2; mi++)
#pragma unroll
            for (int ni = 0; ni < 8; ni++) {
                int np0 = ni * 8 + 2 * qc;               // even, 0..62
                int t0  = tbase + np0;                   // even -> float2 aligned
                int r0  = wid * 32 + mi * 16 + grp;
                if (np0 < NTO && t0 + 1 < TLEN) {
#pragma unroll
                    for (int h = 0; h < 2; h++) {
                        size_t off = (size_t)(r0 + h * 8) * TLEN + t0;
                        float d0 = acc[mi][ni][h * 2], d1 = acc[mi][ni][h * 2 + 1];
                        float2 xr = *(const float2*)(xb + off);
                        __stcs((float2*)(skipb + off), make_float2(d0, d1));
                        __stcs((float2*)(outb  + off), make_float2(d0 + xr.x, d1 + xr.y));
                    }
                } else if (np0 < NTO && t0 < TLEN) {     // single trailing column
#pragma unroll
                    for (int h = 0; h < 2; h++) {
                        size_t off = (size_t)(r0 + h * 8) * TLEN + t0;
                        float d0 = acc[mi][ni][h * 2];
                        __stcs(skipb + off, d0);
                        __stcs(outb  + off, d0 + xb[off]);
                    }
                }
            }
    }
}

extern "C" void kernel_launch(void* const* d_in, const int* in_sizes, int n_in,
                              void* d_out, int out_size) {
    const float* x  = (const float*)d_in[0];
    const float* wf = (const float*)d_in[1];
    const float* wg = (const float*)d_in[2];
    const float* ws = (const float*)d_in[3];

    float* out  = (float*)d_out;
    float* skip = out + (size_t)BB * CC * TLEN;

    cudaFuncSetAttribute(k_fused, cudaFuncAttributeMaxDynamicSharedMemorySize, SMEMF);

    k_transpose<<<(3 * 4096 + 255) / 256, 256>>>(wf, wg, ws);

    dim3 grid(NBLK, BB);
    k_fused<<<grid, 256, SMEMF>>>(x, out, skip);
}